// round 5
// baseline (speedup 1.0000x reference)
#include <cuda_runtime.h>
#include <cuda_bf16.h>
#include <cstdint>

#define N_MAX 50000
#define D 128

// ---- scratch (__device__ globals; no cudaMalloc allowed) -------------------
__device__ float g_agg[N_MAX * D];     // scatter accumulator [N,128]
__device__ int   g_deg_out[N_MAX];
__device__ int   g_deg_in[N_MAX];
__device__ float g_ns[N_MAX];          // rsqrt(max(deg_out,1))
__device__ float g_nd[N_MAX];          // rsqrt(max(deg_in,1))
__device__ float g_bias[D];            // b_conv @ Wa1 + b_aggr
// packed bf16 weights: [phase*64 + kpair][n], phase0 = W_fused, phase1 = Wa2
__device__ unsigned g_Bh[2 * 64 * D];
__device__ unsigned g_Bl[2 * 64 * D];

__device__ __forceinline__ void split_pack(float v0, float v1,
                                           unsigned& hi, unsigned& lo) {
    __nv_bfloat162 h, l;
    h.x = __float2bfloat16(v0);
    h.y = __float2bfloat16(v1);
    l.x = __float2bfloat16(v0 - __bfloat162float(h.x));
    l.y = __float2bfloat16(v1 - __bfloat162float(h.y));
    hi = *(unsigned*)&h;
    lo = *(unsigned*)&l;
}

// ---------------------------------------------------------------------------
// K0: zero agg + degree counters
__global__ void zero_kernel(int n) {
    int i = blockIdx.x * blockDim.x + threadIdx.x;
    int nf4 = n * (D / 4);
    if (i < nf4) ((float4*)g_agg)[i] = make_float4(0.f, 0.f, 0.f, 0.f);
    if (i < n) { g_deg_out[i] = 0; g_deg_in[i] = 0; }
}

// K1: degree histograms
__global__ void deg_kernel(const int* __restrict__ src,
                           const int* __restrict__ dst, int E) {
    int i = blockIdx.x * blockDim.x + threadIdx.x;
    if (i < E) {
        atomicAdd(&g_deg_out[src[i]], 1);
        atomicAdd(&g_deg_in[dst[i]], 1);
    }
}

// K2: normalization factors
__global__ void norm_kernel(int n) {
    int i = blockIdx.x * blockDim.x + threadIdx.x;
    if (i < n) {
        g_ns[i] = rsqrtf(fmaxf((float)g_deg_out[i], 1.0f));
        g_nd[i] = rsqrtf(fmaxf((float)g_deg_in[i], 1.0f));
    }
}

// K3: fused weight prep.
// blocks 0..63:  W_fused rows 2b,2b+1 = Wc[2b{,+1}] @ Wa  -> split -> g_B*[0]
// blocks 64..127: pack Wa2 rows 2(b-64),2(b-64)+1         -> split -> g_B*[1]
// block 128: bias = b_conv @ Wa + b_aggr
__global__ __launch_bounds__(128) void fuse_kernel(
    const float* __restrict__ Wc,
    const float* __restrict__ Wa,
    const float* __restrict__ Wa2,
    const float* __restrict__ bc,
    const float* __restrict__ ba) {
    int j = threadIdx.x;
    int b = blockIdx.x;
    if (b < 64) {
        __shared__ float wrow[2][D];
        wrow[0][j] = Wc[(2 * b) * D + j];
        wrow[1][j] = Wc[(2 * b + 1) * D + j];
        __syncthreads();
        float s0 = 0.f, s1 = 0.f, s2 = 0.f, s3 = 0.f;
#pragma unroll 4
        for (int k = 0; k < D; k += 2) {
            float wa0 = Wa[k * D + j];
            float wa1 = Wa[(k + 1) * D + j];
            s0 += wrow[0][k] * wa0;
            s2 += wrow[0][k + 1] * wa1;
            s1 += wrow[1][k] * wa0;
            s3 += wrow[1][k + 1] * wa1;
        }
        unsigned h, l;
        split_pack(s0 + s2, s1 + s3, h, l);
        g_Bh[b * D + j] = h;
        g_Bl[b * D + j] = l;
    } else if (b < 128) {
        int bb = b - 64;
        float w0 = Wa2[(2 * bb) * D + j];
        float w1 = Wa2[(2 * bb + 1) * D + j];
        unsigned h, l;
        split_pack(w0, w1, h, l);
        g_Bh[(64 + bb) * D + j] = h;
        g_Bl[(64 + bb) * D + j] = l;
    } else {
        float s = ba[j];
        float a0 = 0.f, a1 = 0.f;
#pragma unroll 4
        for (int k = 0; k < D; k += 2) {
            a0 += bc[k] * Wa[k * D + j];
            a1 += bc[k + 1] * Wa[(k + 1) * D + j];
        }
        g_bias[j] = s + a0 + a1;
    }
}

// K4: scatter-add: agg[dst[e]] += X[src[e]] * ns[src[e]]  (one warp per edge)
__global__ __launch_bounds__(256) void scatter_kernel(
    const float4* __restrict__ X4,
    const int* __restrict__ src,
    const int* __restrict__ dst, int E) {
    int gt = blockIdx.x * 256 + threadIdx.x;
    int e = gt >> 5;
    int lane = gt & 31;
    if (e >= E) return;
    int s = __ldg(&src[e]);
    int d = __ldg(&dst[e]);
    float ns = __ldg(&g_ns[s]);
    float4 v = __ldg(&X4[s * 32 + lane]);
    v.x *= ns; v.y *= ns; v.z *= ns; v.w *= ns;
    float4* p = ((float4*)g_agg) + d * 32 + lane;
    asm volatile("red.global.add.v4.f32 [%0], {%1,%2,%3,%4};"
                 :: "l"(p), "f"(v.x), "f"(v.y), "f"(v.z), "f"(v.w)
                 : "memory");
}

// ---------------------------------------------------------------------------
// K5: tensor-core GEMM: out = (agg*nd) @ W_fused + X @ Wa2 + bias
// bf16 error-compensated split (hi*hi + hi*lo + lo*hi), fp32 accumulate.
// Block tile 128m x 128n, K=256 in 4 chunks of 64. 8 warps (2m x 4n),
// warp tile 64m x 32n -> 4x4 m16n8 atoms, 64 fp32 acc regs/thread.
// B comes pre-split/pre-packed from g_Bh/g_Bl (staged as plain uint4 copy).
#define KC 64
#define KPC (KC / 2)       // kpairs per chunk = 32
#define A_STR 33           // sA row stride (u32), pad for bank-free frag reads
#define B_STR 136          // sB row stride (u32), 136 % 32 == 8 -> bank-free
#define SA_SZ (128 * A_STR)
#define SB_SZ (KPC * B_STR)
#define SM_U32 (2 * SA_SZ + 2 * SB_SZ)

#define MMA_BF16(c, a, b)                                                   \
    asm volatile(                                                           \
        "mma.sync.aligned.m16n8k16.row.col.f32.bf16.bf16.f32 "              \
        "{%0,%1,%2,%3}, {%4,%5,%6,%7}, {%8,%9}, {%0,%1,%2,%3};"             \
        : "+f"((c)[0]), "+f"((c)[1]), "+f"((c)[2]), "+f"((c)[3])            \
        : "r"((a)[0]), "r"((a)[1]), "r"((a)[2]), "r"((a)[3]),               \
          "r"((b)[0]), "r"((b)[1]))

__global__ __launch_bounds__(256) void out_gemm_kernel(
    const float* __restrict__ X,
    float* __restrict__ out, int n) {
    extern __shared__ unsigned sm[];
    unsigned* sAh = sm;
    unsigned* sAl = sm + SA_SZ;
    unsigned* sBh = sm + 2 * SA_SZ;
    unsigned* sBl = sm + 2 * SA_SZ + SB_SZ;

    int tid = threadIdx.x;
    int wid = tid >> 5;
    int lane = tid & 31;
    int gid = lane >> 2;     // 0..7
    int tig = lane & 3;      // 0..3
    int wm = wid >> 2;       // 0..1  -> rows 64*wm
    int wn = wid & 3;        // 0..3  -> cols 32*wn
    int row0 = blockIdx.x * 128;

    float acc[4][4][4];
#pragma unroll
    for (int mt = 0; mt < 4; mt++)
#pragma unroll
        for (int nt = 0; nt < 4; nt++)
#pragma unroll
            for (int i = 0; i < 4; i++) acc[mt][nt][i] = 0.f;

#pragma unroll
    for (int phase = 0; phase < 2; phase++) {
        const float* Asrc = (phase == 0) ? g_agg : X;
#pragma unroll
        for (int ch = 0; ch < 2; ch++) {
            int k0 = ch * KC;
            // ---- stage A: 128 rows x 64 cols -> split to bf16 hi/lo ------
#pragma unroll
            for (int it = 0; it < 8; it++) {
                int idx = tid + it * 256;
                int r = idx >> 4;
                int f4 = idx & 15;
                int grow = row0 + r;
                float4 v = make_float4(0.f, 0.f, 0.f, 0.f);
                if (grow < n) {
                    v = ((const float4*)Asrc)[grow * 32 + (k0 >> 2) + f4];
                    if (phase == 0) {
                        float nd = g_nd[grow];
                        v.x *= nd; v.y *= nd; v.z *= nd; v.w *= nd;
                    }
                }
                unsigned h0, l0, h1, l1;
                split_pack(v.x, v.y, h0, l0);
                split_pack(v.z, v.w, h1, l1);
                int o = r * A_STR + f4 * 2;
                sAh[o] = h0; sAh[o + 1] = h1;
                sAl[o] = l0; sAl[o + 1] = l1;
            }
            // ---- stage B: plain uint4 copy of pre-packed weights ----------
            {
                const unsigned* Bh = g_Bh + (phase * 64 + ch * KPC) * D;
                const unsigned* Bl = g_Bl + (phase * 64 + ch * KPC) * D;
#pragma unroll
                for (int it = 0; it < 4; it++) {
                    int idx = tid + it * 256;   // 0..1023 uint4s
                    int kp = idx >> 5;
                    int q = idx & 31;
                    uint4 vh = ((const uint4*)(Bh + kp * D))[q];
                    uint4 vl = ((const uint4*)(Bl + kp * D))[q];
                    *(uint4*)&sBh[kp * B_STR + q * 4] = vh;
                    *(uint4*)&sBl[kp * B_STR + q * 4] = vl;
                }
            }
            __syncthreads();

            // ---- mma over 4 k16 steps ------------------------------------
#pragma unroll
            for (int s = 0; s < 4; s++) {
                int kb = s * 8;  // kpair base
                unsigned bh[4][2], bl[4][2];
#pragma unroll
                for (int nt = 0; nt < 4; nt++) {
                    int col = wn * 32 + nt * 8 + gid;
                    bh[nt][0] = sBh[(kb + tig) * B_STR + col];
                    bh[nt][1] = sBh[(kb + tig + 4) * B_STR + col];
                    bl[nt][0] = sBl[(kb + tig) * B_STR + col];
                    bl[nt][1] = sBl[(kb + tig + 4) * B_STR + col];
                }
#pragma unroll
                for (int mt = 0; mt < 4; mt++) {
                    int rb = wm * 64 + mt * 16;
                    unsigned ah[4], al[4];
                    ah[0] = sAh[(rb + gid) * A_STR + kb + tig];
                    ah[1] = sAh[(rb + gid + 8) * A_STR + kb + tig];
                    ah[2] = sAh[(rb + gid) * A_STR + kb + tig + 4];
                    ah[3] = sAh[(rb + gid + 8) * A_STR + kb + tig + 4];
                    al[0] = sAl[(rb + gid) * A_STR + kb + tig];
                    al[1] = sAl[(rb + gid + 8) * A_STR + kb + tig];
                    al[2] = sAl[(rb + gid) * A_STR + kb + tig + 4];
                    al[3] = sAl[(rb + gid + 8) * A_STR + kb + tig + 4];
#pragma unroll
                    for (int nt = 0; nt < 4; nt++) {
                        MMA_BF16(acc[mt][nt], ah, bh[nt]);  // hi*hi
                        MMA_BF16(acc[mt][nt], ah, bl[nt]);  // hi*lo
                        MMA_BF16(acc[mt][nt], al, bh[nt]);  // lo*hi
                    }
                }
            }
            __syncthreads();
        }
    }

    // ---- epilogue: bias + store ------------------------------------------
#pragma unroll
    for (int mt = 0; mt < 4; mt++) {
        int r = row0 + wm * 64 + mt * 16 + gid;
#pragma unroll
        for (int nt = 0; nt < 4; nt++) {
            int col = wn * 32 + nt * 8 + 2 * tig;
            float2 bv = *(const float2*)&g_bias[col];
            if (r < n) {
                float2 o0 = make_float2(acc[mt][nt][0] + bv.x,
                                        acc[mt][nt][1] + bv.y);
                *(float2*)&out[r * D + col] = o0;
            }
            if (r + 8 < n) {
                float2 o1 = make_float2(acc[mt][nt][2] + bv.x,
                                        acc[mt][nt][3] + bv.y);
                *(float2*)&out[(r + 8) * D + col] = o1;
            }
        }
    }
}

// ---------------------------------------------------------------------------
extern "C" void kernel_launch(void* const* d_in, const int* in_sizes, int n_in,
                              void* d_out, int out_size) {
    const float* features = (const float*)d_in[0];
    const int*   src      = (const int*)d_in[1];
    const int*   dst      = (const int*)d_in[2];
    const float* W_conv   = (const float*)d_in[3];
    const float* b_conv   = (const float*)d_in[4];
    const float* W_aggr   = (const float*)d_in[5];
    const float* b_aggr   = (const float*)d_in[6];
    float* out = (float*)d_out;

    int n = in_sizes[0] / D;
    int E = in_sizes[1];

    cudaFuncSetAttribute(out_gemm_kernel,
                         cudaFuncAttributeMaxDynamicSharedMemorySize,
                         SM_U32 * (int)sizeof(unsigned));

    int nf4 = n * (D / 4);
    zero_kernel<<<(nf4 + 255) / 256, 256>>>(n);
    deg_kernel<<<(E + 255) / 256, 256>>>(src, dst, E);
    norm_kernel<<<(n + 255) / 256, 256>>>(n);
    fuse_kernel<<<129, 128>>>(W_conv, W_aggr, W_aggr + D * D, b_conv, b_aggr);

    long long threads = (long long)E * 32;
    scatter_kernel<<<(int)((threads + 255) / 256), 256>>>(
        (const float4*)features, src, dst, E);

    out_gemm_kernel<<<(n + 127) / 128, 256, SM_U32 * (int)sizeof(unsigned)>>>(
        features, out, n);
}

// round 6
// speedup vs baseline: 1.2615x; 1.2615x over previous
#include <cuda_runtime.h>
#include <cuda_bf16.h>
#include <cstdint>

#define N_MAX 50000
#define D 128

// ---- scratch (__device__ globals; no cudaMalloc allowed) -------------------
__device__ float g_agg[N_MAX * D];     // scatter accumulator [N,128]
__device__ int   g_deg_out[N_MAX];
__device__ int   g_deg_in[N_MAX];
__device__ float g_ns[N_MAX];          // rsqrt(max(deg_out,1))
__device__ float g_nd[N_MAX];          // rsqrt(max(deg_in,1))
__device__ float g_Wfused[D * D];      // W_conv @ W_aggr[0:128]
__device__ float g_bias[D];            // b_conv @ Wa1 + b_aggr

// ---------------------------------------------------------------------------
// K0: zero agg + degree counters
__global__ void zero_kernel(int n) {
    int i = blockIdx.x * blockDim.x + threadIdx.x;
    int nf4 = n * (D / 4);
    if (i < nf4) ((float4*)g_agg)[i] = make_float4(0.f, 0.f, 0.f, 0.f);
    if (i < n) { g_deg_out[i] = 0; g_deg_in[i] = 0; }
}

// K1: degree histograms
__global__ void deg_kernel(const int* __restrict__ src,
                           const int* __restrict__ dst, int E) {
    int i = blockIdx.x * blockDim.x + threadIdx.x;
    if (i < E) {
        atomicAdd(&g_deg_out[src[i]], 1);
        atomicAdd(&g_deg_in[dst[i]], 1);
    }
}

// K2: normalization factors
__global__ void norm_kernel(int n) {
    int i = blockIdx.x * blockDim.x + threadIdx.x;
    if (i < n) {
        g_ns[i] = rsqrtf(fmaxf((float)g_deg_out[i], 1.0f));
        g_nd[i] = rsqrtf(fmaxf((float)g_deg_in[i], 1.0f));
    }
}

// K3: W_fused = Wc @ Wa1, bias = b_conv @ Wa1 + b_aggr.
// One block per output row; 8 independent accumulators + full unroll so
// ptxas front-batches Wa loads (MLP >> 2). Wc row staged via smem.
__global__ __launch_bounds__(128) void fuse_kernel(
    const float* __restrict__ Wc,
    const float* __restrict__ Wa,
    const float* __restrict__ bc,
    const float* __restrict__ ba) {
    __shared__ float wc[D];
    int j = threadIdx.x;
    int b = blockIdx.x;
    // stage the left-operand row (Wc row b, or b_conv for the bias block)
    wc[j] = (b < D) ? __ldg(&Wc[b * D + j]) : __ldg(&bc[j]);
    __syncthreads();

    float a0 = 0.f, a1 = 0.f, a2 = 0.f, a3 = 0.f;
    float a4 = 0.f, a5 = 0.f, a6 = 0.f, a7 = 0.f;
#pragma unroll
    for (int k = 0; k < D; k += 8) {
        a0 += wc[k    ] * __ldg(&Wa[(k    ) * D + j]);
        a1 += wc[k + 1] * __ldg(&Wa[(k + 1) * D + j]);
        a2 += wc[k + 2] * __ldg(&Wa[(k + 2) * D + j]);
        a3 += wc[k + 3] * __ldg(&Wa[(k + 3) * D + j]);
        a4 += wc[k + 4] * __ldg(&Wa[(k + 4) * D + j]);
        a5 += wc[k + 5] * __ldg(&Wa[(k + 5) * D + j]);
        a6 += wc[k + 6] * __ldg(&Wa[(k + 6) * D + j]);
        a7 += wc[k + 7] * __ldg(&Wa[(k + 7) * D + j]);
    }
    float s = ((a0 + a1) + (a2 + a3)) + ((a4 + a5) + (a6 + a7));
    if (b < D) g_Wfused[b * D + j] = s;
    else       g_bias[j] = s + __ldg(&ba[j]);
}

// K4: scatter-add: agg[dst[e]] += X[src[e]] * ns[src[e]]  (one warp per edge)
__global__ __launch_bounds__(256) void scatter_kernel(
    const float4* __restrict__ X4,
    const int* __restrict__ src,
    const int* __restrict__ dst, int E) {
    int gt = blockIdx.x * 256 + threadIdx.x;
    int e = gt >> 5;
    int lane = gt & 31;
    if (e >= E) return;
    int s = __ldg(&src[e]);
    int d = __ldg(&dst[e]);
    float ns = g_ns[s];
    float4 v = X4[s * 32 + lane];
    v.x *= ns; v.y *= ns; v.z *= ns; v.w *= ns;
    float4* p = ((float4*)g_agg) + d * 32 + lane;
    asm volatile("red.global.add.v4.f32 [%0], {%1,%2,%3,%4};"
                 :: "l"(p), "f"(v.x), "f"(v.y), "f"(v.z), "f"(v.w)
                 : "memory");
}

// ---------------------------------------------------------------------------
// K5: tensor-core GEMM: out = (agg*nd) @ W_fused + X @ Wa2 + bias
// (byte-for-byte the round-4 version: in-kernel W split/convert)
#define KC 64
#define KPC (KC / 2)       // kpairs per chunk = 32
#define A_STR 33           // sA row stride (u32), pad for bank-free frag reads
#define B_STR 136          // sB row stride (u32), 136 % 32 == 8 -> bank-free
#define SA_SZ (128 * A_STR)
#define SB_SZ (KPC * B_STR)
#define SM_U32 (2 * SA_SZ + 2 * SB_SZ)

#define MMA_BF16(c, a, b)                                                   \
    asm volatile(                                                           \
        "mma.sync.aligned.m16n8k16.row.col.f32.bf16.bf16.f32 "              \
        "{%0,%1,%2,%3}, {%4,%5,%6,%7}, {%8,%9}, {%0,%1,%2,%3};"             \
        : "+f"((c)[0]), "+f"((c)[1]), "+f"((c)[2]), "+f"((c)[3])            \
        : "r"((a)[0]), "r"((a)[1]), "r"((a)[2]), "r"((a)[3]),               \
          "r"((b)[0]), "r"((b)[1]))

__device__ __forceinline__ void split_pack(float v0, float v1,
                                           unsigned& hi, unsigned& lo) {
    __nv_bfloat162 h, l;
    h.x = __float2bfloat16(v0);
    h.y = __float2bfloat16(v1);
    l.x = __float2bfloat16(v0 - __bfloat162float(h.x));
    l.y = __float2bfloat16(v1 - __bfloat162float(h.y));
    hi = *(unsigned*)&h;
    lo = *(unsigned*)&l;
}

__global__ __launch_bounds__(256) void out_gemm_kernel(
    const float* __restrict__ X,
    const float* __restrict__ Wa2,
    float* __restrict__ out, int n) {
    extern __shared__ unsigned sm[];
    unsigned* sAh = sm;
    unsigned* sAl = sm + SA_SZ;
    unsigned* sBh = sm + 2 * SA_SZ;
    unsigned* sBl = sm + 2 * SA_SZ + SB_SZ;

    int tid = threadIdx.x;
    int wid = tid >> 5;
    int lane = tid & 31;
    int gid = lane >> 2;     // 0..7
    int tig = lane & 3;      // 0..3
    int wm = wid >> 2;       // 0..1  -> rows 64*wm
    int wn = wid & 3;        // 0..3  -> cols 32*wn
    int row0 = blockIdx.x * 128;

    float acc[4][4][4];
#pragma unroll
    for (int mt = 0; mt < 4; mt++)
#pragma unroll
        for (int nt = 0; nt < 4; nt++)
#pragma unroll
            for (int i = 0; i < 4; i++) acc[mt][nt][i] = 0.f;

#pragma unroll
    for (int phase = 0; phase < 2; phase++) {
        const float* Asrc = (phase == 0) ? g_agg : X;
        const float* Wsrc = (phase == 0) ? g_Wfused : Wa2;
#pragma unroll
        for (int ch = 0; ch < 2; ch++) {
            int k0 = ch * KC;
            // ---- stage A: 128 rows x 64 cols -> packed bf16 pairs --------
#pragma unroll
            for (int it = 0; it < 8; it++) {
                int idx = tid + it * 256;
                int r = idx >> 4;
                int f4 = idx & 15;
                int grow = row0 + r;
                float4 v = make_float4(0.f, 0.f, 0.f, 0.f);
                if (grow < n) {
                    v = ((const float4*)Asrc)[grow * 32 + (k0 >> 2) + f4];
                    if (phase == 0) {
                        float nd = g_nd[grow];
                        v.x *= nd; v.y *= nd; v.z *= nd; v.w *= nd;
                    }
                }
                unsigned h0, l0, h1, l1;
                split_pack(v.x, v.y, h0, l0);
                split_pack(v.z, v.w, h1, l1);
                int o = r * A_STR + f4 * 2;
                sAh[o] = h0; sAh[o + 1] = h1;
                sAl[o] = l0; sAl[o + 1] = l1;
            }
            // ---- stage B: 64 k x 128 n -> packed [kpair][n] ---------------
#pragma unroll
            for (int it = 0; it < 16; it++) {
                int idx = tid + it * 256;
                int kp = idx >> 7;
                int nn = idx & 127;
                float w0 = Wsrc[(k0 + 2 * kp) * D + nn];
                float w1 = Wsrc[(k0 + 2 * kp + 1) * D + nn];
                unsigned h, l;
                split_pack(w0, w1, h, l);
                sBh[kp * B_STR + nn] = h;
                sBl[kp * B_STR + nn] = l;
            }
            __syncthreads();

            // ---- mma over 4 k16 steps ------------------------------------
#pragma unroll
            for (int s = 0; s < 4; s++) {
                int kb = s * 8;  // kpair base
                unsigned bh[4][2], bl[4][2];
#pragma unroll
                for (int nt = 0; nt < 4; nt++) {
                    int col = wn * 32 + nt * 8 + gid;
                    bh[nt][0] = sBh[(kb + tig) * B_STR + col];
                    bh[nt][1] = sBh[(kb + tig + 4) * B_STR + col];
                    bl[nt][0] = sBl[(kb + tig) * B_STR + col];
                    bl[nt][1] = sBl[(kb + tig + 4) * B_STR + col];
                }
#pragma unroll
                for (int mt = 0; mt < 4; mt++) {
                    int rb = wm * 64 + mt * 16;
                    unsigned ah[4], al[4];
                    ah[0] = sAh[(rb + gid) * A_STR + kb + tig];
                    ah[1] = sAh[(rb + gid + 8) * A_STR + kb + tig];
                    ah[2] = sAh[(rb + gid) * A_STR + kb + tig + 4];
                    ah[3] = sAh[(rb + gid + 8) * A_STR + kb + tig + 4];
                    al[0] = sAl[(rb + gid) * A_STR + kb + tig];
                    al[1] = sAl[(rb + gid + 8) * A_STR + kb + tig];
                    al[2] = sAl[(rb + gid) * A_STR + kb + tig + 4];
                    al[3] = sAl[(rb + gid + 8) * A_STR + kb + tig + 4];
#pragma unroll
                    for (int nt = 0; nt < 4; nt++) {
                        MMA_BF16(acc[mt][nt], ah, bh[nt]);  // hi*hi
                        MMA_BF16(acc[mt][nt], ah, bl[nt]);  // hi*lo
                        MMA_BF16(acc[mt][nt], al, bh[nt]);  // lo*hi
                    }
                }
            }
            __syncthreads();
        }
    }

    // ---- epilogue: bias + store ------------------------------------------
#pragma unroll
    for (int mt = 0; mt < 4; mt++) {
        int r = row0 + wm * 64 + mt * 16 + gid;
#pragma unroll
        for (int nt = 0; nt < 4; nt++) {
            int col = wn * 32 + nt * 8 + 2 * tig;
            float2 bv = *(const float2*)&g_bias[col];
            if (r < n) {
                float2 o0 = make_float2(acc[mt][nt][0] + bv.x,
                                        acc[mt][nt][1] + bv.y);
                *(float2*)&out[r * D + col] = o0;
            }
            if (r + 8 < n) {
                float2 o1 = make_float2(acc[mt][nt][2] + bv.x,
                                        acc[mt][nt][3] + bv.y);
                *(float2*)&out[(r + 8) * D + col] = o1;
            }
        }
    }
}

// ---------------------------------------------------------------------------
extern "C" void kernel_launch(void* const* d_in, const int* in_sizes, int n_in,
                              void* d_out, int out_size) {
    const float* features = (const float*)d_in[0];
    const int*   src      = (const int*)d_in[1];
    const int*   dst      = (const int*)d_in[2];
    const float* W_conv   = (const float*)d_in[3];
    const float* b_conv   = (const float*)d_in[4];
    const float* W_aggr   = (const float*)d_in[5];
    const float* b_aggr   = (const float*)d_in[6];
    float* out = (float*)d_out;

    int n = in_sizes[0] / D;
    int E = in_sizes[1];

    cudaFuncSetAttribute(out_gemm_kernel,
                         cudaFuncAttributeMaxDynamicSharedMemorySize,
                         SM_U32 * (int)sizeof(unsigned));

    int nf4 = n * (D / 4);
    zero_kernel<<<(nf4 + 255) / 256, 256>>>(n);
    deg_kernel<<<(E + 255) / 256, 256>>>(src, dst, E);
    norm_kernel<<<(n + 255) / 256, 256>>>(n);
    fuse_kernel<<<D + 1, D>>>(W_conv, W_aggr, b_conv, b_aggr);

    long long threads = (long long)E * 32;
    scatter_kernel<<<(int)((threads + 255) / 256), 256>>>(
        (const float4*)features, src, dst, E);

    out_gemm_kernel<<<(n + 127) / 128, 256, SM_U32 * (int)sizeof(unsigned)>>>(
        features, W_aggr + D * D, out, n);
}